// round 1
// baseline (speedup 1.0000x reference)
#include <cuda_runtime.h>
#include <cstdint>

// Problem constants
#define TOK   65536      // B*S = 8*8192
#define DM    512
#define DFF   2048
#define NHEAD 8
#define DH    64
#define WIN   32
#define NWIN  2048       // TOK/WIN
#define EPSLN 1e-5f

// ---------------------------------------------------------------------------
// Scratch (device globals; allocation-free per harness rules)
// ---------------------------------------------------------------------------
__device__ float g_q [(size_t)TOK * DM];
__device__ float g_k [(size_t)TOK * DM];
__device__ float g_v [(size_t)TOK * DM];
__device__ float g_o [(size_t)TOK * DM];
__device__ float g_x1[(size_t)TOK * DM];
__device__ float g_h [(size_t)TOK * DFF];

// ---------------------------------------------------------------------------
// SGEMM: C[M,N] = A[M,K] @ B[K,N] + bias, optional ReLU.
// 128x128 tile, BK=16, 256 threads, 8x8 per thread.
// Requires M%128==0, N%128==0, K%16==0 (true for all our shapes).
// ---------------------------------------------------------------------------
__global__ __launch_bounds__(256) void sgemm_kernel(
    const float* __restrict__ A, const float* __restrict__ B,
    const float* __restrict__ bias, float* __restrict__ C,
    int M, int N, int K, int relu)
{
    __shared__ float As[16][128];
    __shared__ float Bs[16][128];

    const int tid = threadIdx.x;
    const int bm = blockIdx.y;
    const int bn = blockIdx.x;
    const int tm = (tid >> 4) << 3;   // (tid/16)*8
    const int tn = (tid & 15) << 3;   // (tid%16)*8

    float acc[8][8];
#pragma unroll
    for (int i = 0; i < 8; i++)
#pragma unroll
        for (int j = 0; j < 8; j++) acc[i][j] = 0.0f;

    const float* Ab = A + (size_t)bm * 128 * K;
    const float* Bb = B + (size_t)bn * 128;

    for (int k0 = 0; k0 < K; k0 += 16) {
        // Load A tile 128x16 (transposed into As[k][m])
#pragma unroll
        for (int i = 0; i < 2; i++) {
            int lin = tid + i * 256;          // 0..511
            int row = lin >> 2;               // 0..127
            int c4  = lin & 3;                // 0..3
            float4 av = *(const float4*)(Ab + (size_t)row * K + k0 + c4 * 4);
            As[c4 * 4 + 0][row] = av.x;
            As[c4 * 4 + 1][row] = av.y;
            As[c4 * 4 + 2][row] = av.z;
            As[c4 * 4 + 3][row] = av.w;
        }
        // Load B tile 16x128
#pragma unroll
        for (int i = 0; i < 2; i++) {
            int lin = tid + i * 256;
            int row = lin >> 5;               // 0..15
            int c4  = lin & 31;               // 0..31
            *(float4*)&Bs[row][c4 * 4] =
                *(const float4*)(Bb + (size_t)(k0 + row) * N + c4 * 4);
        }
        __syncthreads();

#pragma unroll
        for (int kk = 0; kk < 16; kk++) {
            float a[8], b[8];
#pragma unroll
            for (int i = 0; i < 8; i++) a[i] = As[kk][tm + i];
#pragma unroll
            for (int j = 0; j < 8; j++) b[j] = Bs[kk][tn + j];
#pragma unroll
            for (int i = 0; i < 8; i++)
#pragma unroll
                for (int j = 0; j < 8; j++) acc[i][j] += a[i] * b[j];
        }
        __syncthreads();
    }

    // Epilogue: bias (+ReLU), vectorized stores
    const int ncol = bn * 128 + tn;
    float4 bv0 = *(const float4*)(bias + ncol);
    float4 bv1 = *(const float4*)(bias + ncol + 4);
#pragma unroll
    for (int i = 0; i < 8; i++) {
        float* Crow = C + (size_t)(bm * 128 + tm + i) * N + ncol;
        float4 o0, o1;
        o0.x = acc[i][0] + bv0.x; o0.y = acc[i][1] + bv0.y;
        o0.z = acc[i][2] + bv0.z; o0.w = acc[i][3] + bv0.w;
        o1.x = acc[i][4] + bv1.x; o1.y = acc[i][5] + bv1.y;
        o1.z = acc[i][6] + bv1.z; o1.w = acc[i][7] + bv1.w;
        if (relu) {
            o0.x = fmaxf(o0.x, 0.f); o0.y = fmaxf(o0.y, 0.f);
            o0.z = fmaxf(o0.z, 0.f); o0.w = fmaxf(o0.w, 0.f);
            o1.x = fmaxf(o1.x, 0.f); o1.y = fmaxf(o1.y, 0.f);
            o1.z = fmaxf(o1.z, 0.f); o1.w = fmaxf(o1.w, 0.f);
        }
        *(float4*)(Crow)     = o0;
        *(float4*)(Crow + 4) = o1;
    }
}

// ---------------------------------------------------------------------------
// Window attention: one block per (window, head). 256 threads.
// q,k,v layout: [token, head*64 + d] row-major, token = window*32 + row.
// ---------------------------------------------------------------------------
__global__ __launch_bounds__(256) void window_attn_kernel(
    const float* __restrict__ q, const float* __restrict__ k,
    const float* __restrict__ v, float* __restrict__ o)
{
    const int bid = blockIdx.x;          // 0..NWIN*NHEAD-1
    const int h = bid & (NHEAD - 1);
    const int w = bid >> 3;
    const int t0 = w * WIN;
    const int tid = threadIdx.x;

    __shared__ float qs[WIN][DH];
    __shared__ float ks[WIN][DH];
    __shared__ float vs[WIN][DH];
    __shared__ float sc[WIN][WIN + 1];

    // Load q/k/v tiles: 32x64 floats each = 512 float4 each; 256 threads -> 2 each
#pragma unroll
    for (int i = 0; i < 2; i++) {
        int lin = tid + i * 256;          // 0..511
        int row = lin >> 4;               // 0..31
        int c4  = lin & 15;               // 0..15
        size_t gidx = (size_t)(t0 + row) * DM + h * DH + c4 * 4;
        *(float4*)&qs[row][c4 * 4] = *(const float4*)(q + gidx);
        *(float4*)&ks[row][c4 * 4] = *(const float4*)(k + gidx);
        *(float4*)&vs[row][c4 * 4] = *(const float4*)(v + gidx);
    }
    __syncthreads();

    // Scores: 32x32 = 1024 entries / 256 threads = 4 each
#pragma unroll
    for (int i = 0; i < 4; i++) {
        int lin = tid + i * 256;
        int r = lin >> 5, c = lin & 31;
        float s = 0.f;
#pragma unroll
        for (int d = 0; d < DH; d++) s += qs[r][d] * ks[c][d];
        sc[r][c] = s * 0.125f;            // 1/sqrt(64)
    }
    __syncthreads();

    // Softmax per row: 32 rows, one thread each
    if (tid < WIN) {
        float m = -1e30f;
#pragma unroll
        for (int j = 0; j < WIN; j++) m = fmaxf(m, sc[tid][j]);
        float sum = 0.f;
#pragma unroll
        for (int j = 0; j < WIN; j++) {
            float e = __expf(sc[tid][j] - m);
            sc[tid][j] = e;
            sum += e;
        }
        float inv = 1.0f / sum;
#pragma unroll
        for (int j = 0; j < WIN; j++) sc[tid][j] *= inv;
    }
    __syncthreads();

    // O = attn @ V: 32x64 = 2048 entries / 256 threads = 8 each
#pragma unroll
    for (int i = 0; i < 8; i++) {
        int lin = tid + i * 256;
        int r = lin >> 6, d = lin & 63;
        float s = 0.f;
#pragma unroll
        for (int j = 0; j < WIN; j++) s += sc[r][j] * vs[j][d];
        o[(size_t)(t0 + r) * DM + h * DH + d] = s;
    }
}

// ---------------------------------------------------------------------------
// Fused residual-add + LayerNorm. One block (128 threads) per token row.
// y = LN(x + r) * g + b
// ---------------------------------------------------------------------------
__global__ __launch_bounds__(128) void add_ln_kernel(
    const float* __restrict__ x, const float* __restrict__ r,
    const float* __restrict__ g, const float* __restrict__ b,
    float* __restrict__ y)
{
    const int row = blockIdx.x;
    const int tid = threadIdx.x;

    float4 xv = ((const float4*)(x + (size_t)row * DM))[tid];
    float4 rv = ((const float4*)(r + (size_t)row * DM))[tid];
    float v0 = xv.x + rv.x, v1 = xv.y + rv.y, v2 = xv.z + rv.z, v3 = xv.w + rv.w;

    __shared__ float red[4];
    float s = v0 + v1 + v2 + v3;
#pragma unroll
    for (int off = 16; off > 0; off >>= 1) s += __shfl_xor_sync(0xffffffffu, s, off);
    if ((tid & 31) == 0) red[tid >> 5] = s;
    __syncthreads();
    const float mu = (red[0] + red[1] + red[2] + red[3]) * (1.0f / DM);

    float d0 = v0 - mu, d1 = v1 - mu, d2 = v2 - mu, d3 = v3 - mu;
    float qsum = d0 * d0 + d1 * d1 + d2 * d2 + d3 * d3;
    __syncthreads();   // protect red reuse
#pragma unroll
    for (int off = 16; off > 0; off >>= 1) qsum += __shfl_xor_sync(0xffffffffu, qsum, off);
    if ((tid & 31) == 0) red[tid >> 5] = qsum;
    __syncthreads();
    const float var = (red[0] + red[1] + red[2] + red[3]) * (1.0f / DM);
    const float inv = rsqrtf(var + EPSLN);

    float4 gv = ((const float4*)g)[tid];
    float4 bv = ((const float4*)b)[tid];
    float4 out;
    out.x = d0 * inv * gv.x + bv.x;
    out.y = d1 * inv * gv.y + bv.y;
    out.z = d2 * inv * gv.z + bv.z;
    out.w = d3 * inv * gv.w + bv.w;
    ((float4*)(y + (size_t)row * DM))[tid] = out;
}

// ---------------------------------------------------------------------------
// Launch
// ---------------------------------------------------------------------------
extern "C" void kernel_launch(void* const* d_in, const int* in_sizes, int n_in,
                              void* d_out, int out_size)
{
    (void)in_sizes; (void)n_in; (void)out_size;
    const float* x   = (const float*)d_in[0];
    const float* Wq  = (const float*)d_in[1];
    const float* bq  = (const float*)d_in[2];
    const float* Wk  = (const float*)d_in[3];
    const float* bk  = (const float*)d_in[4];
    const float* Wv  = (const float*)d_in[5];
    const float* bv  = (const float*)d_in[6];
    const float* Wo  = (const float*)d_in[7];
    const float* bo  = (const float*)d_in[8];
    const float* g1  = (const float*)d_in[9];
    const float* be1 = (const float*)d_in[10];
    const float* W1  = (const float*)d_in[11];
    const float* b1  = (const float*)d_in[12];
    const float* W2  = (const float*)d_in[13];
    const float* b2  = (const float*)d_in[14];
    const float* g2  = (const float*)d_in[15];
    const float* be2 = (const float*)d_in[16];
    float* out = (float*)d_out;

    float *q, *k, *v, *o, *x1, *h;
    cudaGetSymbolAddress((void**)&q,  g_q);
    cudaGetSymbolAddress((void**)&k,  g_k);
    cudaGetSymbolAddress((void**)&v,  g_v);
    cudaGetSymbolAddress((void**)&o,  g_o);
    cudaGetSymbolAddress((void**)&x1, g_x1);
    cudaGetSymbolAddress((void**)&h,  g_h);
    float* attn_out = q;   // q dead after attention
    float* ff_out   = k;   // k dead after attention

    dim3 gD (DM  / 128, TOK / 128);   // (4, 512)
    dim3 gFF(DFF / 128, TOK / 128);   // (16, 512)

    // QKV projections
    sgemm_kernel<<<gD, 256>>>(x, Wq, bq, q, TOK, DM, DM, 0);
    sgemm_kernel<<<gD, 256>>>(x, Wk, bk, k, TOK, DM, DM, 0);
    sgemm_kernel<<<gD, 256>>>(x, Wv, bv, v, TOK, DM, DM, 0);

    // Block-local window attention
    window_attn_kernel<<<NWIN * NHEAD, 256>>>(q, k, v, o);

    // Output projection
    sgemm_kernel<<<gD, 256>>>(o, Wo, bo, attn_out, TOK, DM, DM, 0);

    // Residual + LN1
    add_ln_kernel<<<TOK, 128>>>(x, attn_out, g1, be1, x1);

    // FFN
    sgemm_kernel<<<gFF, 256>>>(x1, W1, b1, h, TOK, DFF, DM, 1);
    sgemm_kernel<<<gD, 256>>>(h, W2, b2, ff_out, TOK, DM, DFF, 0);

    // Residual + LN2 -> output
    add_ln_kernel<<<TOK, 128>>>(x1, ff_out, g2, be2, out);
}

// round 2
// speedup vs baseline: 2.7965x; 2.7965x over previous
#include <cuda_runtime.h>
#include <cstdint>

// Problem constants
#define TOK   65536      // B*S = 8*8192
#define DM    512
#define DFF   2048
#define NHEAD 8
#define DH    64
#define WIN   32
#define NWIN  2048       // TOK/WIN
#define EPSLN 1e-5f

// ---------------------------------------------------------------------------
// Scratch (device globals; allocation-free per harness rules)
// ---------------------------------------------------------------------------
__device__ float g_q [(size_t)TOK * DM];
__device__ float g_k [(size_t)TOK * DM];
__device__ float g_v [(size_t)TOK * DM];
__device__ float g_o [(size_t)TOK * DM];
__device__ float g_x1[(size_t)TOK * DM];
__device__ float g_h [(size_t)TOK * DFF];
// Transposed (N-major) weights, tf32-rounded
__device__ float g_wqt[DM * DM];
__device__ float g_wkt[DM * DM];
__device__ float g_wvt[DM * DM];
__device__ float g_wot[DM * DM];
__device__ float g_w1t[(size_t)DFF * DM];   // [2048, 512]
__device__ float g_w2t[(size_t)DM * DFF];   // [512, 2048]

// ---------------------------------------------------------------------------
// Weight transpose with tf32 rounding: W[K,N] -> Wt[N,K]
// ---------------------------------------------------------------------------
__global__ void transpose_tf32_kernel(const float* __restrict__ W,
                                      float* __restrict__ Wt, int K, int N)
{
    __shared__ float t[32][33];
    const int n0 = blockIdx.x * 32, k0 = blockIdx.y * 32;
    const int tx = threadIdx.x, ty = threadIdx.y;
#pragma unroll
    for (int i = ty; i < 32; i += 8)
        t[i][tx] = W[(size_t)(k0 + i) * N + n0 + tx];
    __syncthreads();
#pragma unroll
    for (int i = ty; i < 32; i += 8) {
        float v = t[tx][i];
        uint32_t u;
        asm("cvt.rna.tf32.f32 %0, %1;" : "=r"(u) : "f"(v));
        Wt[(size_t)(n0 + i) * K + k0 + tx] = __uint_as_float(u);
    }
}

// ---------------------------------------------------------------------------
// TF32 tensor-core GEMM: C[M,N] = A[M,K] @ Bt[N,K]^T + bias (opt ReLU)
// CTA tile 128x128, BK=16, 256 threads (8 warps of 32x64), double-buffered
// cp.async, ldmatrix fragment loads, mma.sync.m16n8k8.tf32.
// Requires M%128==0, N%128==0, K%16==0.
// ---------------------------------------------------------------------------
#define BK 16
#define TSTRIDE 20          // floats per smem row (16 data + 4 pad)
#define TILE_F (128 * TSTRIDE)

__device__ __forceinline__ void ldsm_x4(uint32_t r[4], uint32_t addr)
{
    asm volatile("ldmatrix.sync.aligned.m8n8.x4.shared.b16 {%0,%1,%2,%3}, [%4];"
                 : "=r"(r[0]), "=r"(r[1]), "=r"(r[2]), "=r"(r[3]) : "r"(addr));
}

__device__ __forceinline__ void mma_tf32(float c[4], const uint32_t a[4],
                                         const uint32_t b[2])
{
    asm volatile(
        "mma.sync.aligned.m16n8k8.row.col.f32.tf32.tf32.f32 "
        "{%0,%1,%2,%3}, {%4,%5,%6,%7}, {%8,%9}, {%0,%1,%2,%3};"
        : "+f"(c[0]), "+f"(c[1]), "+f"(c[2]), "+f"(c[3])
        : "r"(a[0]), "r"(a[1]), "r"(a[2]), "r"(a[3]), "r"(b[0]), "r"(b[1]));
}

__device__ __forceinline__ void cp16(uint32_t smem, const float* gmem)
{
    asm volatile("cp.async.cg.shared.global [%0], [%1], 16;"
                 :: "r"(smem), "l"(gmem));
}

__global__ __launch_bounds__(256, 2) void tf32_gemm_kernel(
    const float* __restrict__ A, const float* __restrict__ Bt,
    const float* __restrict__ bias, float* __restrict__ C,
    int M, int N, int K, int relu)
{
    __shared__ float As[2][TILE_F];
    __shared__ float Bs[2][TILE_F];

    const int tid = threadIdx.x;
    const int bm = blockIdx.y, bn = blockIdx.x;
    const int wid = tid >> 5, lane = tid & 31;
    const int warp_m = wid & 3;          // 4 m-warps * 32 rows
    const int warp_n = wid >> 2;         // 2 n-warps * 64 cols
    const int gid = lane >> 2, ctid = lane & 3;
    const int mat = lane >> 3, rin = lane & 7;

    // cp.async source/dest indexing (2 chunks per thread per tile per operand)
    const int ldr0 = tid >> 2,        ldc0 = (tid & 3) * 4;
    const int ldr1 = (tid + 256) >> 2, ldc1 = ((tid + 256) & 3) * 4;

    const uint32_t as_base = (uint32_t)__cvta_generic_to_shared(&As[0][0]);
    const uint32_t bs_base = (uint32_t)__cvta_generic_to_shared(&Bs[0][0]);
    const uint32_t buf_bytes = TILE_F * 4;

    // ldmatrix per-lane byte offsets (within a buffer), excluding k-step
    uint32_t a_off[2], b_off[4];
#pragma unroll
    for (int mt = 0; mt < 2; mt++)
        a_off[mt] = ((warp_m * 32 + mt * 16 + (mat & 1) * 8 + rin) * TSTRIDE
                     + (mat >> 1) * 4) * 4;
#pragma unroll
    for (int ntp = 0; ntp < 4; ntp++)
        b_off[ntp] = ((warp_n * 64 + ntp * 16 + (mat >> 1) * 8 + rin) * TSTRIDE
                      + (mat & 1) * 4) * 4;

    float acc[2][8][4];
#pragma unroll
    for (int mt = 0; mt < 2; mt++)
#pragma unroll
        for (int nt = 0; nt < 8; nt++)
#pragma unroll
            for (int i = 0; i < 4; i++) acc[mt][nt][i] = 0.0f;

    const float* Abase = A  + (size_t)(bm * 128) * K;
    const float* Bbase = Bt + (size_t)(bn * 128) * K;
    const int ntiles = K / BK;

    // Prologue: load tile 0 into buffer 0
    {
        cp16(as_base + (ldr0 * TSTRIDE + ldc0) * 4, Abase + (size_t)ldr0 * K + ldc0);
        cp16(as_base + (ldr1 * TSTRIDE + ldc1) * 4, Abase + (size_t)ldr1 * K + ldc1);
        cp16(bs_base + (ldr0 * TSTRIDE + ldc0) * 4, Bbase + (size_t)ldr0 * K + ldc0);
        cp16(bs_base + (ldr1 * TSTRIDE + ldc1) * 4, Bbase + (size_t)ldr1 * K + ldc1);
        asm volatile("cp.async.commit_group;");
    }

    for (int t = 0; t < ntiles; t++) {
        const int buf = t & 1;
        if (t + 1 < ntiles) {
            const int nb = buf ^ 1;
            const int k0 = (t + 1) * BK;
            const float* Ap = Abase + k0;
            const float* Bp = Bbase + k0;
            const uint32_t ao = as_base + nb * buf_bytes;
            const uint32_t bo = bs_base + nb * buf_bytes;
            cp16(ao + (ldr0 * TSTRIDE + ldc0) * 4, Ap + (size_t)ldr0 * K + ldc0);
            cp16(ao + (ldr1 * TSTRIDE + ldc1) * 4, Ap + (size_t)ldr1 * K + ldc1);
            cp16(bo + (ldr0 * TSTRIDE + ldc0) * 4, Bp + (size_t)ldr0 * K + ldc0);
            cp16(bo + (ldr1 * TSTRIDE + ldc1) * 4, Bp + (size_t)ldr1 * K + ldc1);
            asm volatile("cp.async.commit_group;");
            asm volatile("cp.async.wait_group 1;");
        } else {
            asm volatile("cp.async.wait_group 0;");
        }
        __syncthreads();

        const uint32_t ab = as_base + buf * buf_bytes;
        const uint32_t bb = bs_base + buf * buf_bytes;
#pragma unroll
        for (int ks = 0; ks < 2; ks++) {
            const uint32_t kkb = ks * 32;   // 8 floats * 4B
            uint32_t af[2][4];
#pragma unroll
            for (int mt = 0; mt < 2; mt++)
                ldsm_x4(af[mt], ab + a_off[mt] + kkb);
            uint32_t bf[8][2];
#pragma unroll
            for (int ntp = 0; ntp < 4; ntp++) {
                uint32_t q[4];
                ldsm_x4(q, bb + b_off[ntp] + kkb);
                bf[2 * ntp][0] = q[0]; bf[2 * ntp][1] = q[1];
                bf[2 * ntp + 1][0] = q[2]; bf[2 * ntp + 1][1] = q[3];
            }
#pragma unroll
            for (int mt = 0; mt < 2; mt++)
#pragma unroll
                for (int nt = 0; nt < 8; nt++)
                    mma_tf32(acc[mt][nt], af[mt], bf[nt]);
        }
        __syncthreads();
    }

    // Epilogue: bias (+ReLU), float2 stores
#pragma unroll
    for (int mt = 0; mt < 2; mt++) {
        const int r0 = bm * 128 + warp_m * 32 + mt * 16 + gid;
#pragma unroll
        for (int nt = 0; nt < 8; nt++) {
            const int col = bn * 128 + warp_n * 64 + nt * 8 + 2 * ctid;
            const float b0 = bias[col], b1 = bias[col + 1];
            float2 v0, v1;
            v0.x = acc[mt][nt][0] + b0; v0.y = acc[mt][nt][1] + b1;
            v1.x = acc[mt][nt][2] + b0; v1.y = acc[mt][nt][3] + b1;
            if (relu) {
                v0.x = fmaxf(v0.x, 0.f); v0.y = fmaxf(v0.y, 0.f);
                v1.x = fmaxf(v1.x, 0.f); v1.y = fmaxf(v1.y, 0.f);
            }
            *(float2*)(C + (size_t)r0 * N + col)       = v0;
            *(float2*)(C + (size_t)(r0 + 8) * N + col) = v1;
        }
    }
}

// ---------------------------------------------------------------------------
// Window attention: one block per (window, head). 256 threads.
// ---------------------------------------------------------------------------
__global__ __launch_bounds__(256) void window_attn_kernel(
    const float* __restrict__ q, const float* __restrict__ k,
    const float* __restrict__ v, float* __restrict__ o)
{
    const int bid = blockIdx.x;
    const int h = bid & (NHEAD - 1);
    const int w = bid >> 3;
    const int t0 = w * WIN;
    const int tid = threadIdx.x;

    __shared__ float qs[WIN][DH];
    __shared__ float ks[WIN][DH];
    __shared__ float vs[WIN][DH];
    __shared__ float sc[WIN][WIN + 1];

#pragma unroll
    for (int i = 0; i < 2; i++) {
        int lin = tid + i * 256;
        int row = lin >> 4;
        int c4  = lin & 15;
        size_t gidx = (size_t)(t0 + row) * DM + h * DH + c4 * 4;
        *(float4*)&qs[row][c4 * 4] = *(const float4*)(q + gidx);
        *(float4*)&ks[row][c4 * 4] = *(const float4*)(k + gidx);
        *(float4*)&vs[row][c4 * 4] = *(const float4*)(v + gidx);
    }
    __syncthreads();

#pragma unroll
    for (int i = 0; i < 4; i++) {
        int lin = tid + i * 256;
        int r = lin >> 5, c = lin & 31;
        float s = 0.f;
#pragma unroll
        for (int d = 0; d < DH; d++) s += qs[r][d] * ks[c][d];
        sc[r][c] = s * 0.125f;
    }
    __syncthreads();

    if (tid < WIN) {
        float m = -1e30f;
#pragma unroll
        for (int j = 0; j < WIN; j++) m = fmaxf(m, sc[tid][j]);
        float sum = 0.f;
#pragma unroll
        for (int j = 0; j < WIN; j++) {
            float e = __expf(sc[tid][j] - m);
            sc[tid][j] = e;
            sum += e;
        }
        float inv = 1.0f / sum;
#pragma unroll
        for (int j = 0; j < WIN; j++) sc[tid][j] *= inv;
    }
    __syncthreads();

#pragma unroll
    for (int i = 0; i < 8; i++) {
        int lin = tid + i * 256;
        int r = lin >> 6, d = lin & 63;
        float s = 0.f;
#pragma unroll
        for (int j = 0; j < WIN; j++) s += sc[r][j] * vs[j][d];
        o[(size_t)(t0 + r) * DM + h * DH + d] = s;
    }
}

// ---------------------------------------------------------------------------
// Fused residual-add + LayerNorm. One block (128 threads) per token row.
// ---------------------------------------------------------------------------
__global__ __launch_bounds__(128) void add_ln_kernel(
    const float* __restrict__ x, const float* __restrict__ r,
    const float* __restrict__ g, const float* __restrict__ b,
    float* __restrict__ y)
{
    const int row = blockIdx.x;
    const int tid = threadIdx.x;

    float4 xv = ((const float4*)(x + (size_t)row * DM))[tid];
    float4 rv = ((const float4*)(r + (size_t)row * DM))[tid];
    float v0 = xv.x + rv.x, v1 = xv.y + rv.y, v2 = xv.z + rv.z, v3 = xv.w + rv.w;

    __shared__ float red[4];
    float s = v0 + v1 + v2 + v3;
#pragma unroll
    for (int off = 16; off > 0; off >>= 1) s += __shfl_xor_sync(0xffffffffu, s, off);
    if ((tid & 31) == 0) red[tid >> 5] = s;
    __syncthreads();
    const float mu = (red[0] + red[1] + red[2] + red[3]) * (1.0f / DM);

    float d0 = v0 - mu, d1 = v1 - mu, d2 = v2 - mu, d3 = v3 - mu;
    float qsum = d0 * d0 + d1 * d1 + d2 * d2 + d3 * d3;
    __syncthreads();
#pragma unroll
    for (int off = 16; off > 0; off >>= 1) qsum += __shfl_xor_sync(0xffffffffu, qsum, off);
    if ((tid & 31) == 0) red[tid >> 5] = qsum;
    __syncthreads();
    const float var = (red[0] + red[1] + red[2] + red[3]) * (1.0f / DM);
    const float inv = rsqrtf(var + EPSLN);

    float4 gv = ((const float4*)g)[tid];
    float4 bv = ((const float4*)b)[tid];
    float4 out;
    out.x = d0 * inv * gv.x + bv.x;
    out.y = d1 * inv * gv.y + bv.y;
    out.z = d2 * inv * gv.z + bv.z;
    out.w = d3 * inv * gv.w + bv.w;
    ((float4*)(y + (size_t)row * DM))[tid] = out;
}

// ---------------------------------------------------------------------------
// Launch
// ---------------------------------------------------------------------------
extern "C" void kernel_launch(void* const* d_in, const int* in_sizes, int n_in,
                              void* d_out, int out_size)
{
    (void)in_sizes; (void)n_in; (void)out_size;
    const float* x   = (const float*)d_in[0];
    const float* Wq  = (const float*)d_in[1];
    const float* bq  = (const float*)d_in[2];
    const float* Wk  = (const float*)d_in[3];
    const float* bk  = (const float*)d_in[4];
    const float* Wv  = (const float*)d_in[5];
    const float* bv  = (const float*)d_in[6];
    const float* Wo  = (const float*)d_in[7];
    const float* bo  = (const float*)d_in[8];
    const float* g1  = (const float*)d_in[9];
    const float* be1 = (const float*)d_in[10];
    const float* W1  = (const float*)d_in[11];
    const float* b1  = (const float*)d_in[12];
    const float* W2  = (const float*)d_in[13];
    const float* b2  = (const float*)d_in[14];
    const float* g2  = (const float*)d_in[15];
    const float* be2 = (const float*)d_in[16];
    float* out = (float*)d_out;

    float *q, *k, *v, *o, *x1, *h;
    float *wqt, *wkt, *wvt, *wot, *w1t, *w2t;
    cudaGetSymbolAddress((void**)&q,   g_q);
    cudaGetSymbolAddress((void**)&k,   g_k);
    cudaGetSymbolAddress((void**)&v,   g_v);
    cudaGetSymbolAddress((void**)&o,   g_o);
    cudaGetSymbolAddress((void**)&x1,  g_x1);
    cudaGetSymbolAddress((void**)&h,   g_h);
    cudaGetSymbolAddress((void**)&wqt, g_wqt);
    cudaGetSymbolAddress((void**)&wkt, g_wkt);
    cudaGetSymbolAddress((void**)&wvt, g_wvt);
    cudaGetSymbolAddress((void**)&wot, g_wot);
    cudaGetSymbolAddress((void**)&w1t, g_w1t);
    cudaGetSymbolAddress((void**)&w2t, g_w2t);
    float* attn_out = q;   // q dead after attention
    float* ff_out   = k;   // k dead after attention

    // Weight transposes (tf32-rounded)
    {
        dim3 b(32, 8);
        transpose_tf32_kernel<<<dim3(DM / 32,  DM / 32),  b>>>(Wq, wqt, DM,  DM);
        transpose_tf32_kernel<<<dim3(DM / 32,  DM / 32),  b>>>(Wk, wkt, DM,  DM);
        transpose_tf32_kernel<<<dim3(DM / 32,  DM / 32),  b>>>(Wv, wvt, DM,  DM);
        transpose_tf32_kernel<<<dim3(DM / 32,  DM / 32),  b>>>(Wo, wot, DM,  DM);
        transpose_tf32_kernel<<<dim3(DFF / 32, DM / 32),  b>>>(W1, w1t, DM,  DFF);
        transpose_tf32_kernel<<<dim3(DM / 32,  DFF / 32), b>>>(W2, w2t, DFF, DM);
    }

    dim3 gD (DM  / 128, TOK / 128);   // (4, 512)
    dim3 gFF(DFF / 128, TOK / 128);   // (16, 512)

    // QKV projections
    tf32_gemm_kernel<<<gD, 256>>>(x, wqt, bq, q, TOK, DM, DM, 0);
    tf32_gemm_kernel<<<gD, 256>>>(x, wkt, bk, k, TOK, DM, DM, 0);
    tf32_gemm_kernel<<<gD, 256>>>(x, wvt, bv, v, TOK, DM, DM, 0);

    // Block-local window attention
    window_attn_kernel<<<NWIN * NHEAD, 256>>>(q, k, v, o);

    // Output projection
    tf32_gemm_kernel<<<gD, 256>>>(o, wot, bo, attn_out, TOK, DM, DM, 0);

    // Residual + LN1
    add_ln_kernel<<<TOK, 128>>>(x, attn_out, g1, be1, x1);

    // FFN
    tf32_gemm_kernel<<<gFF, 256>>>(x1, w1t, b1, h, TOK, DFF, DM, 1);
    tf32_gemm_kernel<<<gD, 256>>>(h, w2t, b2, ff_out, TOK, DM, DFF, 0);

    // Residual + LN2 -> output
    add_ln_kernel<<<TOK, 128>>>(x1, ff_out, g2, be2, out);
}

// round 3
// speedup vs baseline: 4.8464x; 1.7330x over previous
#include <cuda_runtime.h>
#include <cuda_fp16.h>
#include <cstdint>

// Problem constants
#define TOK   65536      // B*S = 8*8192
#define DM    512
#define DFF   2048
#define NHEAD 8
#define DH    64
#define WIN   32
#define NWIN  2048       // TOK/WIN
#define EPSLN 1e-5f

// ---------------------------------------------------------------------------
// Scratch (device globals; allocation-free per harness rules)
// ---------------------------------------------------------------------------
__device__ __half g_xh [(size_t)TOK * DM];
__device__ __half g_qh [(size_t)TOK * DM];
__device__ __half g_kh [(size_t)TOK * DM];
__device__ __half g_vh [(size_t)TOK * DM];
__device__ __half g_oh [(size_t)TOK * DM];
__device__ __half g_x1h[(size_t)TOK * DM];
__device__ __half g_hh [(size_t)TOK * DFF];
__device__ float  g_f32a[(size_t)TOK * DM];   // attn_out, then ff_out
__device__ float  g_x1 [(size_t)TOK * DM];
// Transposed (N-major) fp16 weights
__device__ __half g_wqt[DM * DM];
__device__ __half g_wkt[DM * DM];
__device__ __half g_wvt[DM * DM];
__device__ __half g_wot[DM * DM];
__device__ __half g_w1t[(size_t)DFF * DM];
__device__ __half g_w2t[(size_t)DM * DFF];

// ---------------------------------------------------------------------------
// fp32 -> fp16 convert (x)
// ---------------------------------------------------------------------------
__global__ void f2h_kernel(const float* __restrict__ x, __half* __restrict__ xh)
{
    size_t i = (size_t)blockIdx.x * blockDim.x + threadIdx.x;
    float4 v = ((const float4*)x)[i];
    __half2 h0 = __floats2half2_rn(v.x, v.y);
    __half2 h1 = __floats2half2_rn(v.z, v.w);
    uint2 u;
    u.x = *(uint32_t*)&h0;
    u.y = *(uint32_t*)&h1;
    ((uint2*)xh)[i] = u;
}

// ---------------------------------------------------------------------------
// Weight transpose with fp16 rounding: W[K,N] fp32 -> Wt[N,K] fp16
// ---------------------------------------------------------------------------
__global__ void transpose_h_kernel(const float* __restrict__ W,
                                   __half* __restrict__ Wt, int K, int N)
{
    __shared__ float t[32][33];
    const int n0 = blockIdx.x * 32, k0 = blockIdx.y * 32;
    const int tx = threadIdx.x, ty = threadIdx.y;
#pragma unroll
    for (int i = ty; i < 32; i += 8)
        t[i][tx] = W[(size_t)(k0 + i) * N + n0 + tx];
    __syncthreads();
#pragma unroll
    for (int i = ty; i < 32; i += 8)
        Wt[(size_t)(n0 + i) * K + k0 + tx] = __float2half_rn(t[tx][i]);
}

// ---------------------------------------------------------------------------
// FP16 tensor-core GEMM: C[M,N] = A[M,K] @ Bt[N,K]^T + bias (opt ReLU)
// A, Bt fp16; accum fp32. Output fp32 (Cf) and/or fp16 (Ch).
// CTA tile 128x128, BK=32 halfs, 256 threads (8 warps of 32x64),
// double-buffered cp.async, ldmatrix, mma.sync.m16n8k16.
// ---------------------------------------------------------------------------
#define BK 32
#define HSTRIDE 40          // halfs per smem row (32 data + 8 pad = 80B)
#define TILE_H (128 * HSTRIDE)

__device__ __forceinline__ void ldsm_x4(uint32_t r[4], uint32_t addr)
{
    asm volatile("ldmatrix.sync.aligned.m8n8.x4.shared.b16 {%0,%1,%2,%3}, [%4];"
                 : "=r"(r[0]), "=r"(r[1]), "=r"(r[2]), "=r"(r[3]) : "r"(addr));
}

__device__ __forceinline__ void mma_f16(float c[4], const uint32_t a[4],
                                        const uint32_t b[2])
{
    asm volatile(
        "mma.sync.aligned.m16n8k16.row.col.f32.f16.f16.f32 "
        "{%0,%1,%2,%3}, {%4,%5,%6,%7}, {%8,%9}, {%0,%1,%2,%3};"
        : "+f"(c[0]), "+f"(c[1]), "+f"(c[2]), "+f"(c[3])
        : "r"(a[0]), "r"(a[1]), "r"(a[2]), "r"(a[3]), "r"(b[0]), "r"(b[1]));
}

__device__ __forceinline__ void cp16(uint32_t smem, const __half* gmem)
{
    asm volatile("cp.async.cg.shared.global [%0], [%1], 16;"
                 :: "r"(smem), "l"(gmem));
}

__global__ __launch_bounds__(256, 2) void h16_gemm_kernel(
    const __half* __restrict__ A, const __half* __restrict__ Bt,
    const float* __restrict__ bias, float* __restrict__ Cf,
    __half* __restrict__ Ch, int M, int N, int K, int relu)
{
    __shared__ __half As[2][TILE_H];
    __shared__ __half Bs[2][TILE_H];

    const int tid = threadIdx.x;
    const int bm = blockIdx.y, bn = blockIdx.x;
    const int wid = tid >> 5, lane = tid & 31;
    const int warp_m = wid & 3;          // 4 m-warps * 32 rows
    const int warp_n = wid >> 2;         // 2 n-warps * 64 cols
    const int gid = lane >> 2, ctid = lane & 3;
    const int mat = lane >> 3, rin = lane & 7;

    // cp.async indices: 512 16B-chunks per tile per operand, 2 per thread
    const int ldr0 = tid >> 2,         ldc0 = (tid & 3) * 8;
    const int ldr1 = (tid + 256) >> 2, ldc1 = ((tid + 256) & 3) * 8;

    const uint32_t as_base = (uint32_t)__cvta_generic_to_shared(&As[0][0]);
    const uint32_t bs_base = (uint32_t)__cvta_generic_to_shared(&Bs[0][0]);
    const uint32_t buf_bytes = TILE_H * 2;

    // ldmatrix per-lane byte offsets (within buffer), excluding k-step
    uint32_t a_off[2], b_off[4];
#pragma unroll
    for (int mt = 0; mt < 2; mt++)
        a_off[mt] = ((warp_m * 32 + mt * 16 + (mat & 1) * 8 + rin) * HSTRIDE
                     + (mat >> 1) * 8) * 2;
#pragma unroll
    for (int ntp = 0; ntp < 4; ntp++)
        b_off[ntp] = ((warp_n * 64 + ntp * 16 + (mat >> 1) * 8 + rin) * HSTRIDE
                      + (mat & 1) * 8) * 2;

    float acc[2][8][4];
#pragma unroll
    for (int mt = 0; mt < 2; mt++)
#pragma unroll
        for (int nt = 0; nt < 8; nt++)
#pragma unroll
            for (int i = 0; i < 4; i++) acc[mt][nt][i] = 0.0f;

    const __half* Abase = A  + (size_t)(bm * 128) * K;
    const __half* Bbase = Bt + (size_t)(bn * 128) * K;
    const int ntiles = K / BK;

    // Prologue
    {
        cp16(as_base + (ldr0 * HSTRIDE + ldc0) * 2, Abase + (size_t)ldr0 * K + ldc0);
        cp16(as_base + (ldr1 * HSTRIDE + ldc1) * 2, Abase + (size_t)ldr1 * K + ldc1);
        cp16(bs_base + (ldr0 * HSTRIDE + ldc0) * 2, Bbase + (size_t)ldr0 * K + ldc0);
        cp16(bs_base + (ldr1 * HSTRIDE + ldc1) * 2, Bbase + (size_t)ldr1 * K + ldc1);
        asm volatile("cp.async.commit_group;");
    }

    for (int t = 0; t < ntiles; t++) {
        const int buf = t & 1;
        if (t + 1 < ntiles) {
            const int nb = buf ^ 1;
            const int k0 = (t + 1) * BK;
            const __half* Ap = Abase + k0;
            const __half* Bp = Bbase + k0;
            const uint32_t ao = as_base + nb * buf_bytes;
            const uint32_t bo = bs_base + nb * buf_bytes;
            cp16(ao + (ldr0 * HSTRIDE + ldc0) * 2, Ap + (size_t)ldr0 * K + ldc0);
            cp16(ao + (ldr1 * HSTRIDE + ldc1) * 2, Ap + (size_t)ldr1 * K + ldc1);
            cp16(bo + (ldr0 * HSTRIDE + ldc0) * 2, Bp + (size_t)ldr0 * K + ldc0);
            cp16(bo + (ldr1 * HSTRIDE + ldc1) * 2, Bp + (size_t)ldr1 * K + ldc1);
            asm volatile("cp.async.commit_group;");
            asm volatile("cp.async.wait_group 1;");
        } else {
            asm volatile("cp.async.wait_group 0;");
        }
        __syncthreads();

        const uint32_t ab = as_base + buf * buf_bytes;
        const uint32_t bb = bs_base + buf * buf_bytes;
#pragma unroll
        for (int ks = 0; ks < 2; ks++) {
            const uint32_t kkb = ks * 32;   // 16 halfs * 2B
            uint32_t af[2][4];
#pragma unroll
            for (int mt = 0; mt < 2; mt++)
                ldsm_x4(af[mt], ab + a_off[mt] + kkb);
            uint32_t bf[8][2];
#pragma unroll
            for (int ntp = 0; ntp < 4; ntp++) {
                uint32_t qd[4];
                ldsm_x4(qd, bb + b_off[ntp] + kkb);
                bf[2 * ntp][0]     = qd[0]; bf[2 * ntp][1]     = qd[1];
                bf[2 * ntp + 1][0] = qd[2]; bf[2 * ntp + 1][1] = qd[3];
            }
#pragma unroll
            for (int mt = 0; mt < 2; mt++)
#pragma unroll
                for (int nt = 0; nt < 8; nt++)
                    mma_f16(acc[mt][nt], af[mt], bf[nt]);
        }
        __syncthreads();
    }

    // Epilogue: bias (+ReLU) -> fp32 and/or fp16 outputs
#pragma unroll
    for (int mt = 0; mt < 2; mt++) {
        const int r0 = bm * 128 + warp_m * 32 + mt * 16 + gid;
#pragma unroll
        for (int nt = 0; nt < 8; nt++) {
            const int col = bn * 128 + warp_n * 64 + nt * 8 + 2 * ctid;
            const float b0 = bias[col], b1 = bias[col + 1];
            float2 v0, v1;
            v0.x = acc[mt][nt][0] + b0; v0.y = acc[mt][nt][1] + b1;
            v1.x = acc[mt][nt][2] + b0; v1.y = acc[mt][nt][3] + b1;
            if (relu) {
                v0.x = fmaxf(v0.x, 0.f); v0.y = fmaxf(v0.y, 0.f);
                v1.x = fmaxf(v1.x, 0.f); v1.y = fmaxf(v1.y, 0.f);
            }
            if (Cf) {
                *(float2*)(Cf + (size_t)r0 * N + col)       = v0;
                *(float2*)(Cf + (size_t)(r0 + 8) * N + col) = v1;
            }
            if (Ch) {
                __half2 h0 = __floats2half2_rn(v0.x, v0.y);
                __half2 h1 = __floats2half2_rn(v1.x, v1.y);
                *(__half2*)(Ch + (size_t)r0 * N + col)       = h0;
                *(__half2*)(Ch + (size_t)(r0 + 8) * N + col) = h1;
            }
        }
    }
}

// ---------------------------------------------------------------------------
// Window attention (fp16 in/out, fp32 math, conflict-free padded smem)
// One block per (window, head). 256 threads.
// ---------------------------------------------------------------------------
__global__ __launch_bounds__(256) void window_attn_kernel(
    const __half* __restrict__ q, const __half* __restrict__ k,
    const __half* __restrict__ v, __half* __restrict__ o)
{
    const int bid = blockIdx.x;
    const int h = bid & (NHEAD - 1);
    const int w = bid >> 3;
    const int t0 = w * WIN;
    const int tid = threadIdx.x;

    __shared__ float qs[WIN][DH + 1];
    __shared__ float ks[WIN][DH + 1];
    __shared__ float vs[WIN][DH + 1];
    __shared__ float sc[WIN][WIN + 1];

    // Load q/k/v tiles: 32x64 halfs = 2048 halfs = 256 x (8 halfs). 1 per thread.
    {
        const int row = tid >> 3;
        const int h8 = (tid & 7) * 8;
        const size_t gidx = (size_t)(t0 + row) * DM + h * DH + h8;
        uint4 uq = *(const uint4*)(q + gidx);
        uint4 uk = *(const uint4*)(k + gidx);
        uint4 uv = *(const uint4*)(v + gidx);
        const __half2* hq = (const __half2*)&uq;
        const __half2* hk = (const __half2*)&uk;
        const __half2* hv = (const __half2*)&uv;
#pragma unroll
        for (int j = 0; j < 4; j++) {
            float2 fq = __half22float2(hq[j]);
            float2 fk = __half22float2(hk[j]);
            float2 fv = __half22float2(hv[j]);
            qs[row][h8 + 2 * j]     = fq.x; qs[row][h8 + 2 * j + 1] = fq.y;
            ks[row][h8 + 2 * j]     = fk.x; ks[row][h8 + 2 * j + 1] = fk.y;
            vs[row][h8 + 2 * j]     = fv.x; vs[row][h8 + 2 * j + 1] = fv.y;
        }
    }
    __syncthreads();

    // Scores: 1024 entries / 256 threads = 4 each
#pragma unroll
    for (int i = 0; i < 4; i++) {
        int lin = tid + i * 256;
        int r = lin >> 5, c = lin & 31;
        float s = 0.f;
#pragma unroll
        for (int d = 0; d < DH; d++) s += qs[r][d] * ks[c][d];
        sc[r][c] = s * 0.125f;
    }
    __syncthreads();

    // Softmax per row
    if (tid < WIN) {
        float m = -1e30f;
#pragma unroll
        for (int j = 0; j < WIN; j++) m = fmaxf(m, sc[tid][j]);
        float sum = 0.f;
#pragma unroll
        for (int j = 0; j < WIN; j++) {
            float e = __expf(sc[tid][j] - m);
            sc[tid][j] = e;
            sum += e;
        }
        float inv = 1.0f / sum;
#pragma unroll
        for (int j = 0; j < WIN; j++) sc[tid][j] *= inv;
    }
    __syncthreads();

    // O = attn @ V: 2048 entries / 256 threads = 8 each; write half2
#pragma unroll
    for (int i = 0; i < 4; i++) {
        int lin = tid + i * 256;          // covers 1024 half2 slots
        int r = lin >> 5, d2 = (lin & 31) * 2;
        float s0 = 0.f, s1 = 0.f;
#pragma unroll
        for (int j = 0; j < WIN; j++) {
            float a = sc[r][j];
            s0 += a * vs[j][d2];
            s1 += a * vs[j][d2 + 1];
        }
        *(__half2*)(o + (size_t)(t0 + r) * DM + h * DH + d2) =
            __floats2half2_rn(s0, s1);
    }
}

// ---------------------------------------------------------------------------
// Fused residual-add + LayerNorm. One block (128 threads) per token row.
// y fp32; optional fp16 copy yh.
// ---------------------------------------------------------------------------
__global__ __launch_bounds__(128) void add_ln_kernel(
    const float* __restrict__ x, const float* __restrict__ r,
    const float* __restrict__ g, const float* __restrict__ b,
    float* __restrict__ y, __half* __restrict__ yh)
{
    const int row = blockIdx.x;
    const int tid = threadIdx.x;

    float4 xv = ((const float4*)(x + (size_t)row * DM))[tid];
    float4 rv = ((const float4*)(r + (size_t)row * DM))[tid];
    float v0 = xv.x + rv.x, v1 = xv.y + rv.y, v2 = xv.z + rv.z, v3 = xv.w + rv.w;

    __shared__ float red[4];
    float s = v0 + v1 + v2 + v3;
#pragma unroll
    for (int off = 16; off > 0; off >>= 1) s += __shfl_xor_sync(0xffffffffu, s, off);
    if ((tid & 31) == 0) red[tid >> 5] = s;
    __syncthreads();
    const float mu = (red[0] + red[1] + red[2] + red[3]) * (1.0f / DM);

    float d0 = v0 - mu, d1 = v1 - mu, d2 = v2 - mu, d3 = v3 - mu;
    float qsum = d0 * d0 + d1 * d1 + d2 * d2 + d3 * d3;
    __syncthreads();
#pragma unroll
    for (int off = 16; off > 0; off >>= 1) qsum += __shfl_xor_sync(0xffffffffu, qsum, off);
    if ((tid & 31) == 0) red[tid >> 5] = qsum;
    __syncthreads();
    const float var = (red[0] + red[1] + red[2] + red[3]) * (1.0f / DM);
    const float inv = rsqrtf(var + EPSLN);

    float4 gv = ((const float4*)g)[tid];
    float4 bv = ((const float4*)b)[tid];
    float4 out;
    out.x = d0 * inv * gv.x + bv.x;
    out.y = d1 * inv * gv.y + bv.y;
    out.z = d2 * inv * gv.z + bv.z;
    out.w = d3 * inv * gv.w + bv.w;
    ((float4*)(y + (size_t)row * DM))[tid] = out;
    if (yh) {
        __half2 h0 = __floats2half2_rn(out.x, out.y);
        __half2 h1 = __floats2half2_rn(out.z, out.w);
        uint2 u;
        u.x = *(uint32_t*)&h0;
        u.y = *(uint32_t*)&h1;
        ((uint2*)(yh + (size_t)row * DM))[tid] = u;
    }
}

// ---------------------------------------------------------------------------
// Launch
// ---------------------------------------------------------------------------
extern "C" void kernel_launch(void* const* d_in, const int* in_sizes, int n_in,
                              void* d_out, int out_size)
{
    (void)in_sizes; (void)n_in; (void)out_size;
    const float* x   = (const float*)d_in[0];
    const float* Wq  = (const float*)d_in[1];
    const float* bq  = (const float*)d_in[2];
    const float* Wk  = (const float*)d_in[3];
    const float* bk  = (const float*)d_in[4];
    const float* Wv  = (const float*)d_in[5];
    const float* bv  = (const float*)d_in[6];
    const float* Wo  = (const float*)d_in[7];
    const float* bo  = (const float*)d_in[8];
    const float* g1  = (const float*)d_in[9];
    const float* be1 = (const float*)d_in[10];
    const float* W1  = (const float*)d_in[11];
    const float* b1  = (const float*)d_in[12];
    const float* W2  = (const float*)d_in[13];
    const float* b2  = (const float*)d_in[14];
    const float* g2  = (const float*)d_in[15];
    const float* be2 = (const float*)d_in[16];
    float* out = (float*)d_out;

    __half *xh, *qh, *kh, *vh, *oh, *x1h, *hh;
    float *f32a, *x1;
    __half *wqt, *wkt, *wvt, *wot, *w1t, *w2t;
    cudaGetSymbolAddress((void**)&xh,   g_xh);
    cudaGetSymbolAddress((void**)&qh,   g_qh);
    cudaGetSymbolAddress((void**)&kh,   g_kh);
    cudaGetSymbolAddress((void**)&vh,   g_vh);
    cudaGetSymbolAddress((void**)&oh,   g_oh);
    cudaGetSymbolAddress((void**)&x1h,  g_x1h);
    cudaGetSymbolAddress((void**)&hh,   g_hh);
    cudaGetSymbolAddress((void**)&f32a, g_f32a);
    cudaGetSymbolAddress((void**)&x1,   g_x1);
    cudaGetSymbolAddress((void**)&wqt,  g_wqt);
    cudaGetSymbolAddress((void**)&wkt,  g_wkt);
    cudaGetSymbolAddress((void**)&wvt,  g_wvt);
    cudaGetSymbolAddress((void**)&wot,  g_wot);
    cudaGetSymbolAddress((void**)&w1t,  g_w1t);
    cudaGetSymbolAddress((void**)&w2t,  g_w2t);

    // Convert x to fp16; transpose+convert weights
    f2h_kernel<<<(TOK * DM / 4) / 256, 256>>>(x, xh);
    {
        dim3 b(32, 8);
        transpose_h_kernel<<<dim3(DM / 32,  DM / 32),  b>>>(Wq, wqt, DM,  DM);
        transpose_h_kernel<<<dim3(DM / 32,  DM / 32),  b>>>(Wk, wkt, DM,  DM);
        transpose_h_kernel<<<dim3(DM / 32,  DM / 32),  b>>>(Wv, wvt, DM,  DM);
        transpose_h_kernel<<<dim3(DM / 32,  DM / 32),  b>>>(Wo, wot, DM,  DM);
        transpose_h_kernel<<<dim3(DFF / 32, DM / 32),  b>>>(W1, w1t, DM,  DFF);
        transpose_h_kernel<<<dim3(DM / 32,  DFF / 32), b>>>(W2, w2t, DFF, DM);
    }

    dim3 gD (DM  / 128, TOK / 128);   // (4, 512)
    dim3 gFF(DFF / 128, TOK / 128);   // (16, 512)

    // QKV projections -> fp16
    h16_gemm_kernel<<<gD, 256>>>(xh, wqt, bq, nullptr, qh, TOK, DM, DM, 0);
    h16_gemm_kernel<<<gD, 256>>>(xh, wkt, bk, nullptr, kh, TOK, DM, DM, 0);
    h16_gemm_kernel<<<gD, 256>>>(xh, wvt, bv, nullptr, vh, TOK, DM, DM, 0);

    // Block-local window attention (fp16 -> fp16)
    window_attn_kernel<<<NWIN * NHEAD, 256>>>(qh, kh, vh, oh);

    // Output projection -> fp32 (for residual)
    h16_gemm_kernel<<<gD, 256>>>(oh, wot, bo, f32a, nullptr, TOK, DM, DM, 0);

    // Residual + LN1 -> x1 (fp32) + x1h (fp16)
    add_ln_kernel<<<TOK, 128>>>(x, f32a, g1, be1, x1, x1h);

    // FFN
    h16_gemm_kernel<<<gFF, 256>>>(x1h, w1t, b1, nullptr, hh, TOK, DFF, DM, 1);
    h16_gemm_kernel<<<gD, 256>>>(hh, w2t, b2, f32a, nullptr, TOK, DM, DFF, 0);

    // Residual + LN2 -> output (fp32)
    add_ln_kernel<<<TOK, 128>>>(x1, f32a, g2, be2, out, nullptr);
}

// round 4
// speedup vs baseline: 5.6260x; 1.1609x over previous
#include <cuda_runtime.h>
#include <cuda_fp16.h>
#include <cstdint>

// Problem constants
#define TOK   65536      // B*S = 8*8192
#define DM    512
#define DQKV  1536
#define DFF   2048
#define NHEAD 8
#define DH    64
#define WIN   32
#define NWIN  2048       // TOK/WIN
#define EPSLN 1e-5f

// ---------------------------------------------------------------------------
// Scratch (device globals; allocation-free per harness rules)
// ---------------------------------------------------------------------------
__device__ __half g_xh  [(size_t)TOK * DM];
__device__ __half g_qkvh[(size_t)TOK * DQKV];
__device__ __half g_oh  [(size_t)TOK * DM];
__device__ __half g_x1h [(size_t)TOK * DM];
__device__ __half g_hh  [(size_t)TOK * DFF];
__device__ float  g_f32a[(size_t)TOK * DM];   // attn_out, then ff_out
__device__ float  g_x1  [(size_t)TOK * DM];
// Transposed (N-major) fp16 weights
__device__ __half g_wqkvt[(size_t)DQKV * DM];  // rows: q[0,512) k[512,1024) v[1024,1536)
__device__ __half g_wot  [DM * DM];
__device__ __half g_w1t  [(size_t)DFF * DM];
__device__ __half g_w2t  [(size_t)DM * DFF];
__device__ float  g_bqkv [DQKV];

// ---------------------------------------------------------------------------
// fp32 -> fp16 convert
// ---------------------------------------------------------------------------
__global__ void f2h_kernel(const float* __restrict__ x, __half* __restrict__ xh)
{
    size_t i = (size_t)blockIdx.x * blockDim.x + threadIdx.x;
    float4 v = ((const float4*)x)[i];
    __half2 h0 = __floats2half2_rn(v.x, v.y);
    __half2 h1 = __floats2half2_rn(v.z, v.w);
    uint2 u;
    u.x = *(uint32_t*)&h0;
    u.y = *(uint32_t*)&h1;
    ((uint2*)xh)[i] = u;
}

// Concat 3 bias vectors of length DM into bqkv
__global__ void bias_concat_kernel(const float* __restrict__ bq,
                                   const float* __restrict__ bk,
                                   const float* __restrict__ bv,
                                   float* __restrict__ bqkv)
{
    int i = blockIdx.x * blockDim.x + threadIdx.x;   // 0..1535
    const float* src = (i < DM) ? bq : (i < 2 * DM) ? bk : bv;
    bqkv[i] = src[i & (DM - 1)];
}

// ---------------------------------------------------------------------------
// Weight transpose with fp16 rounding: W[K,N] fp32 -> Wt[N,K] fp16
// ---------------------------------------------------------------------------
__global__ void transpose_h_kernel(const float* __restrict__ W,
                                   __half* __restrict__ Wt, int K, int N)
{
    __shared__ float t[32][33];
    const int n0 = blockIdx.x * 32, k0 = blockIdx.y * 32;
    const int tx = threadIdx.x, ty = threadIdx.y;
#pragma unroll
    for (int i = ty; i < 32; i += 8)
        t[i][tx] = W[(size_t)(k0 + i) * N + n0 + tx];
    __syncthreads();
#pragma unroll
    for (int i = ty; i < 32; i += 8)
        Wt[(size_t)(n0 + i) * K + k0 + tx] = __float2half_rn(t[tx][i]);
}

// ---------------------------------------------------------------------------
// FP16 tensor-core GEMM: C[M,N] = A[M,K] @ Bt[N,K]^T + bias (opt ReLU)
// CTA tile 128x128, BK=64 halfs, 256 threads (8 warps of 32x64 warp-tiles),
// double-buffered cp.async in DYNAMIC smem, ldmatrix, mma.sync.m16n8k16.
// ---------------------------------------------------------------------------
#define BK 64
#define HSTRIDE 72                     // halfs per smem row (64 data + 8 pad)
#define ABUF_BYTES (128 * HSTRIDE * 2) // 18432 B per stage per operand
#define GEMM_SMEM (4 * ABUF_BYTES)     // 73728 B total (2 stages x 2 operands)

__device__ __forceinline__ void ldsm_x4(uint32_t r[4], uint32_t addr)
{
    asm volatile("ldmatrix.sync.aligned.m8n8.x4.shared.b16 {%0,%1,%2,%3}, [%4];"
                 : "=r"(r[0]), "=r"(r[1]), "=r"(r[2]), "=r"(r[3]) : "r"(addr));
}

__device__ __forceinline__ void mma_f16(float c[4], const uint32_t a[4],
                                        const uint32_t b[2])
{
    asm volatile(
        "mma.sync.aligned.m16n8k16.row.col.f32.f16.f16.f32 "
        "{%0,%1,%2,%3}, {%4,%5,%6,%7}, {%8,%9}, {%0,%1,%2,%3};"
        : "+f"(c[0]), "+f"(c[1]), "+f"(c[2]), "+f"(c[3])
        : "r"(a[0]), "r"(a[1]), "r"(a[2]), "r"(a[3]), "r"(b[0]), "r"(b[1]));
}

__device__ __forceinline__ void cp16(uint32_t smem, const __half* gmem)
{
    asm volatile("cp.async.cg.shared.global [%0], [%1], 16;"
                 :: "r"(smem), "l"(gmem));
}

__global__ __launch_bounds__(256, 2) void h16_gemm_kernel(
    const __half* __restrict__ A, const __half* __restrict__ Bt,
    const float* __restrict__ bias, float* __restrict__ Cf,
    __half* __restrict__ Ch, int M, int N, int K, int relu)
{
    extern __shared__ __half smem_dyn[];

    const int tid = threadIdx.x;
    const int bm = blockIdx.y, bn = blockIdx.x;
    const int wid = tid >> 5, lane = tid & 31;
    const int warp_m = wid & 3;          // 4 m-warps * 32 rows
    const int warp_n = wid >> 2;         // 2 n-warps * 64 cols
    const int gid = lane >> 2, ctid = lane & 3;
    const int mat = lane >> 3, rin = lane & 7;

    const uint32_t s_base  = (uint32_t)__cvta_generic_to_shared(smem_dyn);
    const uint32_t as_base = s_base;                   // 2 A stages
    const uint32_t bs_base = s_base + 2 * ABUF_BYTES;  // 2 B stages

    // cp.async indices: 1024 16B-chunks per tile per operand, 4 per thread
    int ldr[4], ldc[4];
#pragma unroll
    for (int i = 0; i < 4; i++) {
        int c = tid + i * 256;
        ldr[i] = c >> 3;
        ldc[i] = (c & 7) * 8;
    }

    // ldmatrix per-lane byte offsets (within a stage buffer), excluding k-step
    uint32_t a_off[2], b_off[4];
#pragma unroll
    for (int mt = 0; mt < 2; mt++)
        a_off[mt] = ((warp_m * 32 + mt * 16 + (mat & 1) * 8 + rin) * HSTRIDE
                     + (mat >> 1) * 8) * 2;
#pragma unroll
    for (int ntp = 0; ntp < 4; ntp++)
        b_off[ntp] = ((warp_n * 64 + ntp * 16 + (mat >> 1) * 8 + rin) * HSTRIDE
                      + (mat & 1) * 8) * 2;

    float acc[2][8][4];
#pragma unroll
    for (int mt = 0; mt < 2; mt++)
#pragma unroll
        for (int nt = 0; nt < 8; nt++)
#pragma unroll
            for (int i = 0; i < 4; i++) acc[mt][nt][i] = 0.0f;

    const __half* Abase = A  + (size_t)(bm * 128) * K;
    const __half* Bbase = Bt + (size_t)(bn * 128) * K;
    const int ntiles = K / BK;

    // Prologue: tile 0 -> stage 0
    {
#pragma unroll
        for (int i = 0; i < 4; i++) {
            cp16(as_base + (ldr[i] * HSTRIDE + ldc[i]) * 2,
                 Abase + (size_t)ldr[i] * K + ldc[i]);
            cp16(bs_base + (ldr[i] * HSTRIDE + ldc[i]) * 2,
                 Bbase + (size_t)ldr[i] * K + ldc[i]);
        }
        asm volatile("cp.async.commit_group;");
    }

    for (int t = 0; t < ntiles; t++) {
        const int buf = t & 1;
        if (t + 1 < ntiles) {
            const int nb = buf ^ 1;
            const int k0 = (t + 1) * BK;
            const __half* Ap = Abase + k0;
            const __half* Bp = Bbase + k0;
            const uint32_t ao = as_base + nb * ABUF_BYTES;
            const uint32_t bo = bs_base + nb * ABUF_BYTES;
#pragma unroll
            for (int i = 0; i < 4; i++) {
                cp16(ao + (ldr[i] * HSTRIDE + ldc[i]) * 2,
                     Ap + (size_t)ldr[i] * K + ldc[i]);
                cp16(bo + (ldr[i] * HSTRIDE + ldc[i]) * 2,
                     Bp + (size_t)ldr[i] * K + ldc[i]);
            }
            asm volatile("cp.async.commit_group;");
            asm volatile("cp.async.wait_group 1;");
        } else {
            asm volatile("cp.async.wait_group 0;");
        }
        __syncthreads();

        const uint32_t ab = as_base + buf * ABUF_BYTES;
        const uint32_t bb = bs_base + buf * ABUF_BYTES;
#pragma unroll
        for (int ks = 0; ks < 4; ks++) {
            const uint32_t kkb = ks * 32;   // 16 halfs * 2B
            uint32_t af[2][4];
#pragma unroll
            for (int mt = 0; mt < 2; mt++)
                ldsm_x4(af[mt], ab + a_off[mt] + kkb);
            uint32_t bf[8][2];
#pragma unroll
            for (int ntp = 0; ntp < 4; ntp++) {
                uint32_t qd[4];
                ldsm_x4(qd, bb + b_off[ntp] + kkb);
                bf[2 * ntp][0]     = qd[0]; bf[2 * ntp][1]     = qd[1];
                bf[2 * ntp + 1][0] = qd[2]; bf[2 * ntp + 1][1] = qd[3];
            }
#pragma unroll
            for (int mt = 0; mt < 2; mt++)
#pragma unroll
                for (int nt = 0; nt < 8; nt++)
                    mma_f16(acc[mt][nt], af[mt], bf[nt]);
        }
        __syncthreads();
    }

    // Epilogue: bias (+ReLU) -> fp32 and/or fp16 outputs
#pragma unroll
    for (int mt = 0; mt < 2; mt++) {
        const int r0 = bm * 128 + warp_m * 32 + mt * 16 + gid;
#pragma unroll
        for (int nt = 0; nt < 8; nt++) {
            const int col = bn * 128 + warp_n * 64 + nt * 8 + 2 * ctid;
            const float b0 = bias[col], b1 = bias[col + 1];
            float2 v0, v1;
            v0.x = acc[mt][nt][0] + b0; v0.y = acc[mt][nt][1] + b1;
            v1.x = acc[mt][nt][2] + b0; v1.y = acc[mt][nt][3] + b1;
            if (relu) {
                v0.x = fmaxf(v0.x, 0.f); v0.y = fmaxf(v0.y, 0.f);
                v1.x = fmaxf(v1.x, 0.f); v1.y = fmaxf(v1.y, 0.f);
            }
            if (Cf) {
                *(float2*)(Cf + (size_t)r0 * N + col)       = v0;
                *(float2*)(Cf + (size_t)(r0 + 8) * N + col) = v1;
            }
            if (Ch) {
                __half2 h0 = __floats2half2_rn(v0.x, v0.y);
                __half2 h1 = __floats2half2_rn(v1.x, v1.y);
                *(__half2*)(Ch + (size_t)r0 * N + col)       = h0;
                *(__half2*)(Ch + (size_t)(r0 + 8) * N + col) = h1;
            }
        }
    }
}

// ---------------------------------------------------------------------------
// Window attention (reads packed qkv [TOK, 1536], writes oh [TOK, 512])
// One block per (window, head). 256 threads.
// ---------------------------------------------------------------------------
__global__ __launch_bounds__(256) void window_attn_kernel(
    const __half* __restrict__ qkv, __half* __restrict__ o)
{
    const int bid = blockIdx.x;
    const int h = bid & (NHEAD - 1);
    const int w = bid >> 3;
    const int t0 = w * WIN;
    const int tid = threadIdx.x;

    __shared__ float qs[WIN][DH + 1];
    __shared__ float ks[WIN][DH + 1];
    __shared__ float vs[WIN][DH + 1];
    __shared__ float sc[WIN][WIN + 1];

    // Load q/k/v tiles: 32 rows x 64 halfs each; 256 threads, 8 halfs each.
    {
        const int row = tid >> 3;
        const int h8 = (tid & 7) * 8;
        const size_t base = (size_t)(t0 + row) * DQKV + h * DH + h8;
        uint4 uq = *(const uint4*)(qkv + base);
        uint4 uk = *(const uint4*)(qkv + base + DM);
        uint4 uv = *(const uint4*)(qkv + base + 2 * DM);
        const __half2* hq = (const __half2*)&uq;
        const __half2* hk = (const __half2*)&uk;
        const __half2* hv = (const __half2*)&uv;
#pragma unroll
        for (int j = 0; j < 4; j++) {
            float2 fq = __half22float2(hq[j]);
            float2 fk = __half22float2(hk[j]);
            float2 fv = __half22float2(hv[j]);
            qs[row][h8 + 2 * j]     = fq.x; qs[row][h8 + 2 * j + 1] = fq.y;
            ks[row][h8 + 2 * j]     = fk.x; ks[row][h8 + 2 * j + 1] = fk.y;
            vs[row][h8 + 2 * j]     = fv.x; vs[row][h8 + 2 * j + 1] = fv.y;
        }
    }
    __syncthreads();

    // Scores
#pragma unroll
    for (int i = 0; i < 4; i++) {
        int lin = tid + i * 256;
        int r = lin >> 5, c = lin & 31;
        float s = 0.f;
#pragma unroll
        for (int d = 0; d < DH; d++) s += qs[r][d] * ks[c][d];
        sc[r][c] = s * 0.125f;
    }
    __syncthreads();

    // Softmax per row
    if (tid < WIN) {
        float m = -1e30f;
#pragma unroll
        for (int j = 0; j < WIN; j++) m = fmaxf(m, sc[tid][j]);
        float sum = 0.f;
#pragma unroll
        for (int j = 0; j < WIN; j++) {
            float e = __expf(sc[tid][j] - m);
            sc[tid][j] = e;
            sum += e;
        }
        float inv = 1.0f / sum;
#pragma unroll
        for (int j = 0; j < WIN; j++) sc[tid][j] *= inv;
    }
    __syncthreads();

    // O = attn @ V
#pragma unroll
    for (int i = 0; i < 4; i++) {
        int lin = tid + i * 256;
        int r = lin >> 5, d2 = (lin & 31) * 2;
        float s0 = 0.f, s1 = 0.f;
#pragma unroll
        for (int j = 0; j < WIN; j++) {
            float a = sc[r][j];
            s0 += a * vs[j][d2];
            s1 += a * vs[j][d2 + 1];
        }
        *(__half2*)(o + (size_t)(t0 + r) * DM + h * DH + d2) =
            __floats2half2_rn(s0, s1);
    }
}

// ---------------------------------------------------------------------------
// Fused residual-add + LayerNorm. One block (128 threads) per token row.
// ---------------------------------------------------------------------------
__global__ __launch_bounds__(128) void add_ln_kernel(
    const float* __restrict__ x, const float* __restrict__ r,
    const float* __restrict__ g, const float* __restrict__ b,
    float* __restrict__ y, __half* __restrict__ yh)
{
    const int row = blockIdx.x;
    const int tid = threadIdx.x;

    float4 xv = ((const float4*)(x + (size_t)row * DM))[tid];
    float4 rv = ((const float4*)(r + (size_t)row * DM))[tid];
    float v0 = xv.x + rv.x, v1 = xv.y + rv.y, v2 = xv.z + rv.z, v3 = xv.w + rv.w;

    __shared__ float red[4];
    float s = v0 + v1 + v2 + v3;
#pragma unroll
    for (int off = 16; off > 0; off >>= 1) s += __shfl_xor_sync(0xffffffffu, s, off);
    if ((tid & 31) == 0) red[tid >> 5] = s;
    __syncthreads();
    const float mu = (red[0] + red[1] + red[2] + red[3]) * (1.0f / DM);

    float d0 = v0 - mu, d1 = v1 - mu, d2 = v2 - mu, d3 = v3 - mu;
    float qsum = d0 * d0 + d1 * d1 + d2 * d2 + d3 * d3;
    __syncthreads();
#pragma unroll
    for (int off = 16; off > 0; off >>= 1) qsum += __shfl_xor_sync(0xffffffffu, qsum, off);
    if ((tid & 31) == 0) red[tid >> 5] = qsum;
    __syncthreads();
    const float var = (red[0] + red[1] + red[2] + red[3]) * (1.0f / DM);
    const float inv = rsqrtf(var + EPSLN);

    float4 gv = ((const float4*)g)[tid];
    float4 bv = ((const float4*)b)[tid];
    float4 out;
    out.x = d0 * inv * gv.x + bv.x;
    out.y = d1 * inv * gv.y + bv.y;
    out.z = d2 * inv * gv.z + bv.z;
    out.w = d3 * inv * gv.w + bv.w;
    ((float4*)(y + (size_t)row * DM))[tid] = out;
    if (yh) {
        __half2 h0 = __floats2half2_rn(out.x, out.y);
        __half2 h1 = __floats2half2_rn(out.z, out.w);
        uint2 u;
        u.x = *(uint32_t*)&h0;
        u.y = *(uint32_t*)&h1;
        ((uint2*)(yh + (size_t)row * DM))[tid] = u;
    }
}

// ---------------------------------------------------------------------------
// Launch
// ---------------------------------------------------------------------------
extern "C" void kernel_launch(void* const* d_in, const int* in_sizes, int n_in,
                              void* d_out, int out_size)
{
    (void)in_sizes; (void)n_in; (void)out_size;
    const float* x   = (const float*)d_in[0];
    const float* Wq  = (const float*)d_in[1];
    const float* bq  = (const float*)d_in[2];
    const float* Wk  = (const float*)d_in[3];
    const float* bk  = (const float*)d_in[4];
    const float* Wv  = (const float*)d_in[5];
    const float* bv  = (const float*)d_in[6];
    const float* Wo  = (const float*)d_in[7];
    const float* bo  = (const float*)d_in[8];
    const float* g1  = (const float*)d_in[9];
    const float* be1 = (const float*)d_in[10];
    const float* W1  = (const float*)d_in[11];
    const float* b1  = (const float*)d_in[12];
    const float* W2  = (const float*)d_in[13];
    const float* b2  = (const float*)d_in[14];
    const float* g2  = (const float*)d_in[15];
    const float* be2 = (const float*)d_in[16];
    float* out = (float*)d_out;

    __half *xh, *qkvh, *oh, *x1h, *hh;
    float *f32a, *x1, *bqkv;
    __half *wqkvt, *wot, *w1t, *w2t;
    cudaGetSymbolAddress((void**)&xh,    g_xh);
    cudaGetSymbolAddress((void**)&qkvh,  g_qkvh);
    cudaGetSymbolAddress((void**)&oh,    g_oh);
    cudaGetSymbolAddress((void**)&x1h,   g_x1h);
    cudaGetSymbolAddress((void**)&hh,    g_hh);
    cudaGetSymbolAddress((void**)&f32a,  g_f32a);
    cudaGetSymbolAddress((void**)&x1,    g_x1);
    cudaGetSymbolAddress((void**)&wqkvt, g_wqkvt);
    cudaGetSymbolAddress((void**)&wot,   g_wot);
    cudaGetSymbolAddress((void**)&w1t,   g_w1t);
    cudaGetSymbolAddress((void**)&w2t,   g_w2t);
    cudaGetSymbolAddress((void**)&bqkv,  g_bqkv);

    // One-time attribute set for dynamic smem (idempotent, not a stream op)
    cudaFuncSetAttribute(h16_gemm_kernel,
                         cudaFuncAttributeMaxDynamicSharedMemorySize, GEMM_SMEM);

    // Convert x; transpose+convert weights; concat qkv bias
    f2h_kernel<<<(TOK * DM / 4) / 256, 256>>>(x, xh);
    {
        dim3 b(32, 8);
        transpose_h_kernel<<<dim3(DM / 32,  DM / 32),  b>>>(Wq, wqkvt,                DM,  DM);
        transpose_h_kernel<<<dim3(DM / 32,  DM / 32),  b>>>(Wk, wqkvt + 512 * DM,     DM,  DM);
        transpose_h_kernel<<<dim3(DM / 32,  DM / 32),  b>>>(Wv, wqkvt + 1024 * DM,    DM,  DM);
        transpose_h_kernel<<<dim3(DM / 32,  DM / 32),  b>>>(Wo, wot, DM,  DM);
        transpose_h_kernel<<<dim3(DFF / 32, DM / 32),  b>>>(W1, w1t, DM,  DFF);
        transpose_h_kernel<<<dim3(DM / 32,  DFF / 32), b>>>(W2, w2t, DFF, DM);
        bias_concat_kernel<<<DQKV / 256, 256>>>(bq, bk, bv, bqkv);
    }

    dim3 gQKV(DQKV / 128, TOK / 128);  // (12, 512)
    dim3 gD  (DM   / 128, TOK / 128);  // (4, 512)
    dim3 gFF (DFF  / 128, TOK / 128);  // (16, 512)

    // Fused QKV projection -> qkvh [TOK, 1536]
    h16_gemm_kernel<<<gQKV, 256, GEMM_SMEM>>>(xh, wqkvt, bqkv, nullptr, qkvh,
                                              TOK, DQKV, DM, 0);

    // Block-local window attention
    window_attn_kernel<<<NWIN * NHEAD, 256>>>(qkvh, oh);

    // Output projection -> fp32 (for residual)
    h16_gemm_kernel<<<gD, 256, GEMM_SMEM>>>(oh, wot, bo, f32a, nullptr,
                                            TOK, DM, DM, 0);

    // Residual + LN1 -> x1 (fp32) + x1h (fp16)
    add_ln_kernel<<<TOK, 128>>>(x, f32a, g1, be1, x1, x1h);

    // FFN
    h16_gemm_kernel<<<gFF, 256, GEMM_SMEM>>>(x1h, w1t, b1, nullptr, hh,
                                             TOK, DFF, DM, 1);
    h16_gemm_kernel<<<gD, 256, GEMM_SMEM>>>(hh, w2t, b2, f32a, nullptr,
                                            TOK, DM, DFF, 0);

    // Residual + LN2 -> output (fp32)
    add_ln_kernel<<<TOK, 128>>>(x1, f32a, g2, be2, out, nullptr);
}